// round 9
// baseline (speedup 1.0000x reference)
#include <cuda_runtime.h>
#include <math.h>

// Problem constants
#define T_STEPS 16384
#define HDIM    1024
#define XDIM    256

// Recurrent kernel config
#define NCTA          128   // persistent CTAs (co-resident in wave 1)
#define ROWS_PER_CTA  8     // HDIM / NCTA
#define RNN_THREADS   288   // 8 compute warps + 1 combiner warp (CTA 0 only)
#define NGRP          16    // arrival counter groups (8 CTAs each)
#define NGO           8     // replicated go lines (16 CTAs each)
#define LINE_INTS     32    // 128B line stride
#define WATCHDOG_POLLS 2000000

// Scratch (device globals: allocation-free per harness rules)
__device__ float g_bx[(size_t)T_STEPS * HDIM];              // Bx_c, 64 MB
__device__ int   g_cntg[(size_t)T_STEPS * NGRP * LINE_INTS]; // spread counters, 32 MB
__device__ int   g_go[NGO * LINE_INTS];                      // go lines (accumulate)
__device__ int   g_abort;

// ---------------------------------------------------------------------------
// helpers
// ---------------------------------------------------------------------------
__device__ __forceinline__ int atom_acqrel_add(int* p, int v) {
    int old;
    asm volatile("atom.acq_rel.gpu.global.add.s32 %0, [%1], %2;"
                 : "=r"(old) : "l"(p), "r"(v) : "memory");
    return old;
}

__device__ __forceinline__ void red_release_add(int* p, int v) {
    asm volatile("red.release.gpu.global.add.s32 [%0], %1;"
                 :: "l"(p), "r"(v) : "memory");
}

__device__ __forceinline__ int ldcg_i32(const int* p) {
    int v;
    asm volatile("ld.global.cg.s32 %0, [%1];" : "=r"(v) : "l"(p) : "memory");
    return v;
}

__device__ __forceinline__ void stg_i32(int* p, int v) {
    asm volatile("st.global.s32 [%0], %1;" :: "l"(p), "r"(v) : "memory");
}

__device__ __forceinline__ void bar_compute() {      // warps 0-7 only
    asm volatile("bar.sync 1, 256;" ::: "memory");
}

__device__ __forceinline__ float warp_sum(float v) {
#pragma unroll
    for (int s = 16; s > 0; s >>= 1)
        v += __shfl_xor_sync(0xffffffffu, v, s);
    return v;
}

// ---------------------------------------------------------------------------
// 0) zero counters + go + abort (graph replays reuse device globals)
// ---------------------------------------------------------------------------
__global__ void init_cnt_kernel() {
    size_t i = (size_t)blockIdx.x * blockDim.x + threadIdx.x;
    size_t n = (size_t)T_STEPS * NGRP * LINE_INTS;
    for (size_t k = i; k < n; k += (size_t)gridDim.x * blockDim.x)
        g_cntg[k] = 0;
    if (i < NGO * LINE_INTS) g_go[i] = 0;
    if (i == 0) g_abort = 0;
}

// ---------------------------------------------------------------------------
// 1) Bx_c = x_seq @ B^T + c   (T x H), fp32 tiled GEMM
// ---------------------------------------------------------------------------
__global__ __launch_bounds__(256) void gemm_bx_kernel(
    const float* __restrict__ x,   // (T, 256)
    const float* __restrict__ B,   // (1024, 256)
    const float* __restrict__ c)   // (1024,)
{
    __shared__ float xsT[32][132];
    __shared__ float bsT[32][68];

    const int bj  = blockIdx.x * 64;
    const int bt  = blockIdx.y * 128;
    const int tid = threadIdx.x;
    const int tx  = tid & 15;
    const int ty  = tid >> 4;

    float acc[8][4];
#pragma unroll
    for (int i = 0; i < 8; i++)
#pragma unroll
        for (int j = 0; j < 4; j++) acc[i][j] = 0.0f;

    for (int k0 = 0; k0 < XDIM; k0 += 32) {
#pragma unroll
        for (int i = 0; i < 4; i++) {
            int idx = tid + i * 256;
            int r   = idx >> 3;
            int kk4 = (idx & 7) * 4;
            float4 v = *(const float4*)&x[(size_t)(bt + r) * XDIM + k0 + kk4];
            xsT[kk4 + 0][r] = v.x; xsT[kk4 + 1][r] = v.y;
            xsT[kk4 + 2][r] = v.z; xsT[kk4 + 3][r] = v.w;
        }
#pragma unroll
        for (int i = 0; i < 2; i++) {
            int idx = tid + i * 256;
            int r   = idx >> 3;
            int kk4 = (idx & 7) * 4;
            float4 v = *(const float4*)&B[(size_t)(bj + r) * XDIM + k0 + kk4];
            bsT[kk4 + 0][r] = v.x; bsT[kk4 + 1][r] = v.y;
            bsT[kk4 + 2][r] = v.z; bsT[kk4 + 3][r] = v.w;
        }
        __syncthreads();

#pragma unroll
        for (int kk = 0; kk < 32; kk++) {
            float xr[8], br[4];
#pragma unroll
            for (int i = 0; i < 8; i++) xr[i] = xsT[kk][ty * 8 + i];
#pragma unroll
            for (int j = 0; j < 4; j++) br[j] = bsT[kk][tx * 4 + j];
#pragma unroll
            for (int i = 0; i < 8; i++)
#pragma unroll
                for (int j = 0; j < 4; j++)
                    acc[i][j] = fmaf(xr[i], br[j], acc[i][j]);
        }
        __syncthreads();
    }

#pragma unroll
    for (int i = 0; i < 8; i++) {
        int t = bt + ty * 8 + i;
#pragma unroll
        for (int j = 0; j < 4; j++) {
            int col = bj + tx * 4 + j;
            g_bx[(size_t)t * HDIM + col] = acc[i][j] + c[col];
        }
    }
}

// ---------------------------------------------------------------------------
// 2) persistent recurrent kernel: TREE barrier, all-atomic (FIFO-fair).
//    Arrivals: CTA b red.release.add -> counter group b>>3 (16 counters,
//    8 arrivals each = 216 cyc serialize instead of 128*27=3.4k).
//    Combiner: warp 8 of CTA 0; 16 lanes atomic-poll the 16 counters in
//    parallel (1 poller each), then lanes 0-7 red.release.add the 8 go lines.
//    Consumers: thread0 polls go[b>>4] with atom.acq_rel(+0) (16 pollers/line).
// ---------------------------------------------------------------------------
__global__ __launch_bounds__(RNN_THREADS, 1) void rnn_scan_kernel(
    const float* __restrict__ A_raw,  // (1024, 1024)
    const float* __restrict__ h0,     // (1024,)
    float* __restrict__ out)          // (16384, 1024)
{
    const int b = blockIdx.x;
    const int w = threadIdx.x >> 5;
    const int l = threadIdx.x & 31;

    // ---------------- combiner warp ----------------
    if (w == 8) {
        if (b != 0) return;
        const int  g      = (l < NGRP) ? l : 0;
        const bool active = (l < NGRP);
        for (int t = 0; t < T_STEPS; t++) {
            int* cp = &g_cntg[((size_t)t * NGRP + g) * LINE_INTS];
            int polls = 0;
            bool ab = false;
            for (;;) {
                int v = active ? atom_acqrel_add(cp, 0) : ROWS_PER_CTA;
                if (__all_sync(0xffffffffu, v >= 8)) break;   // 8 CTAs per group
                if ((++polls & 255) == 0) {
                    if (ldcg_i32(&g_abort) || polls > WATCHDOG_POLLS) {
                        if (l == 0) stg_i32(&g_abort, 1);
                        ab = true;
                        break;
                    }
                }
            }
            if (__any_sync(0xffffffffu, ab)) return;
            if (l < NGO) red_release_add(&g_go[l * LINE_INTS], 1);  // release step t
        }
        return;
    }

    // ---------------- compute warps (0-7) ----------------
    __shared__ int s_abort;
    const int row = b * ROWS_PER_CTA + w;
    if (threadIdx.x == 0) s_abort = 0;

    // Load A row segment into registers, applying A = 0.9*I + 0.1*A_raw
    float4 a[8];
#pragma unroll
    for (int i = 0; i < 8; i++) {
        int col  = 32 * l + 4 * i;
        float4 v = *(const float4*)&A_raw[(size_t)row * HDIM + col];
        v.x *= 0.1f; v.y *= 0.1f; v.z *= 0.1f; v.w *= 0.1f;
        int d = row - col;
        if (d == 0) v.x += 0.9f;
        else if (d == 1) v.y += 0.9f;
        else if (d == 2) v.z += 0.9f;
        else if (d == 3) v.w += 0.9f;
        a[i] = v;
    }
    bar_compute();

    const float* hprev = h0;
    int* my_go  = &g_go[(b >> 4) * LINE_INTS];
    int* my_cnt_base = 0;  // computed per step

    for (int t = 0; t < T_STEPS; t++) {
        // bias prefetch (independent of h -> overlaps wait)
        float bxv = 0.0f;
        if (l == 0) bxv = g_bx[(size_t)t * HDIM + row];

        if (t > 0) {
            if (threadIdx.x == 0) {
                int polls = 0;
                for (;;) {
                    if (atom_acqrel_add(my_go, 0) >= t) break;  // acq_rel = ordering
                    if ((++polls & 255) == 0) {
                        if (ldcg_i32(&g_abort) || polls > WATCHDOG_POLLS) {
                            stg_i32(&g_abort, 1);
                            s_abort = 1;
                            break;
                        }
                    }
                }
            }
            bar_compute();
            if (s_abort) return;   // uniform exit: fallback recomputes
            hprev = out + (size_t)(t - 1) * HDIM;
        }

        // dot product: 32 contiguous elements per lane
        const float4* h4 = (const float4*)(hprev + 32 * l);
        float a0 = 0.f, a1 = 0.f, a2 = 0.f, a3 = 0.f;
#pragma unroll
        for (int i = 0; i < 8; i++) {
            float4 hv = h4[i];
            a0 = fmaf(a[i].x, hv.x, a0);
            a1 = fmaf(a[i].y, hv.y, a1);
            a2 = fmaf(a[i].z, hv.z, a2);
            a3 = fmaf(a[i].w, hv.w, a3);
        }
        float acc = warp_sum((a0 + a1) + (a2 + a3));

        if (l == 0) {
            out[(size_t)t * HDIM + row] = tanhf(acc + bxv);
        }

        bar_compute();   // all 8 rows stored before arrival
        if (threadIdx.x == 0) {
            red_release_add(&g_cntg[((size_t)t * NGRP + (b >> 3)) * LINE_INTS], 1);
        }
    }
}

// ---------------------------------------------------------------------------
// 3) fallback: single-CTA full recompute; runs only if g_abort was set.
// ---------------------------------------------------------------------------
__global__ __launch_bounds__(1024) void fallback_scan_kernel(
    const float* __restrict__ A_raw,
    const float* __restrict__ h0,
    float* __restrict__ out)
{
    if (g_abort == 0) return;

    __shared__ float h[HDIM];
    __shared__ float hn[HDIM];
    const int tid = threadIdx.x;
    const int w   = tid >> 5;
    const int l   = tid & 31;

    h[tid] = h0[tid];
    __syncthreads();

    for (int t = 0; t < T_STEPS; t++) {
        for (int r = w; r < HDIM; r += 32) {
            const float* Ar = A_raw + (size_t)r * HDIM;
            float acc = 0.0f;
#pragma unroll 8
            for (int k = l; k < HDIM; k += 32)
                acc = fmaf(Ar[k], h[k], acc);
#pragma unroll
            for (int s = 16; s > 0; s >>= 1)
                acc += __shfl_xor_sync(0xffffffffu, acc, s);
            if (l == 0) {
                float v = tanhf(0.1f * acc + 0.9f * h[r] +
                                g_bx[(size_t)t * HDIM + r]);
                hn[r] = v;
                out[(size_t)t * HDIM + r] = v;
            }
        }
        __syncthreads();
        h[tid] = hn[tid];
        __syncthreads();
    }
}

// ---------------------------------------------------------------------------
// launch
// ---------------------------------------------------------------------------
extern "C" void kernel_launch(void* const* d_in, const int* in_sizes, int n_in,
                              void* d_out, int out_size) {
    const float* x_seq = (const float*)d_in[0];  // (16384, 256)
    const float* h0    = (const float*)d_in[1];  // (1024,)
    const float* A_raw = (const float*)d_in[2];  // (1024, 1024)
    const float* B     = (const float*)d_in[3];  // (1024, 256)
    const float* c     = (const float*)d_in[4];  // (1024,)
    float* out = (float*)d_out;                  // (16384, 1024)

    init_cnt_kernel<<<256, 1024>>>();
    gemm_bx_kernel<<<dim3(HDIM / 64, T_STEPS / 128), 256>>>(x_seq, B, c);
    rnn_scan_kernel<<<NCTA, RNN_THREADS>>>(A_raw, h0, out);
    fallback_scan_kernel<<<1, 1024>>>(A_raw, h0, out);
}

// round 10
// speedup vs baseline: 1.0336x; 1.0336x over previous
#include <cuda_runtime.h>
#include <math.h>

// Problem constants
#define T_STEPS 16384
#define HDIM    1024
#define XDIM    256

// Recurrent kernel config
#define NCTA          32    // fewer CTAs => cheaper barrier (arrival serialize ~NCTA*27)
#define ROWS_PER_CTA  32    // HDIM / NCTA
#define RNN_THREADS   512   // 16 warps, 2 rows per warp
#define LINE_INTS     32    // one counter per 128B line
#define WATCHDOG_POLLS 1000000
#define POLL_SLEEP_NS  100

// Scratch (device globals: allocation-free per harness rules)
__device__ float g_bx[(size_t)T_STEPS * HDIM];              // Bx_c, 64 MB
__device__ int   g_cnt[(size_t)T_STEPS * LINE_INTS];        // 1 counter/line, 2 MB
__device__ int   g_abort;

// ---------------------------------------------------------------------------
// helpers
// ---------------------------------------------------------------------------
__device__ __forceinline__ void red_release_add(int* p, int v) {
    asm volatile("red.release.gpu.global.add.s32 [%0], %1;"
                 :: "l"(p), "r"(v) : "memory");
}

__device__ __forceinline__ int ldcg_i32(const int* p) {
    int v;
    asm volatile("ld.global.cg.s32 %0, [%1];" : "=r"(v) : "l"(p) : "memory");
    return v;
}

__device__ __forceinline__ void stg_i32(int* p, int v) {
    asm volatile("st.global.s32 [%0], %1;" :: "l"(p), "r"(v) : "memory");
}

__device__ __forceinline__ void fence_acq() {
    asm volatile("fence.acq_rel.gpu;" ::: "memory");
}

__device__ __forceinline__ float warp_sum(float v) {
#pragma unroll
    for (int s = 16; s > 0; s >>= 1)
        v += __shfl_xor_sync(0xffffffffu, v, s);
    return v;
}

// ---------------------------------------------------------------------------
// 0) zero counters + abort (graph replays reuse device globals -> re-init)
// ---------------------------------------------------------------------------
__global__ void init_cnt_kernel() {
    size_t i = (size_t)blockIdx.x * blockDim.x + threadIdx.x;
    size_t n = (size_t)T_STEPS * LINE_INTS;
    for (size_t k = i; k < n; k += (size_t)gridDim.x * blockDim.x)
        g_cnt[k] = 0;
    if (i == 0) g_abort = 0;
}

// ---------------------------------------------------------------------------
// 1) Bx_c = x_seq @ B^T + c   (T x H), fp32 tiled GEMM
// ---------------------------------------------------------------------------
__global__ __launch_bounds__(256) void gemm_bx_kernel(
    const float* __restrict__ x,   // (T, 256)
    const float* __restrict__ B,   // (1024, 256)
    const float* __restrict__ c)   // (1024,)
{
    __shared__ float xsT[32][132];
    __shared__ float bsT[32][68];

    const int bj  = blockIdx.x * 64;
    const int bt  = blockIdx.y * 128;
    const int tid = threadIdx.x;
    const int tx  = tid & 15;
    const int ty  = tid >> 4;

    float acc[8][4];
#pragma unroll
    for (int i = 0; i < 8; i++)
#pragma unroll
        for (int j = 0; j < 4; j++) acc[i][j] = 0.0f;

    for (int k0 = 0; k0 < XDIM; k0 += 32) {
#pragma unroll
        for (int i = 0; i < 4; i++) {
            int idx = tid + i * 256;
            int r   = idx >> 3;
            int kk4 = (idx & 7) * 4;
            float4 v = *(const float4*)&x[(size_t)(bt + r) * XDIM + k0 + kk4];
            xsT[kk4 + 0][r] = v.x; xsT[kk4 + 1][r] = v.y;
            xsT[kk4 + 2][r] = v.z; xsT[kk4 + 3][r] = v.w;
        }
#pragma unroll
        for (int i = 0; i < 2; i++) {
            int idx = tid + i * 256;
            int r   = idx >> 3;
            int kk4 = (idx & 7) * 4;
            float4 v = *(const float4*)&B[(size_t)(bj + r) * XDIM + k0 + kk4];
            bsT[kk4 + 0][r] = v.x; bsT[kk4 + 1][r] = v.y;
            bsT[kk4 + 2][r] = v.z; bsT[kk4 + 3][r] = v.w;
        }
        __syncthreads();

#pragma unroll
        for (int kk = 0; kk < 32; kk++) {
            float xr[8], br[4];
#pragma unroll
            for (int i = 0; i < 8; i++) xr[i] = xsT[kk][ty * 8 + i];
#pragma unroll
            for (int j = 0; j < 4; j++) br[j] = bsT[kk][tx * 4 + j];
#pragma unroll
            for (int i = 0; i < 8; i++)
#pragma unroll
                for (int j = 0; j < 4; j++)
                    acc[i][j] = fmaf(xr[i], br[j], acc[i][j]);
        }
        __syncthreads();
    }

#pragma unroll
    for (int i = 0; i < 8; i++) {
        int t = bt + ty * 8 + i;
#pragma unroll
        for (int j = 0; j < 4; j++) {
            int col = bj + tx * 4 + j;
            g_bx[(size_t)t * HDIM + col] = acc[i][j] + c[col];
        }
    }
}

// ---------------------------------------------------------------------------
// 2) persistent recurrent kernel: 32 CTAs, one-level barrier.
//    CTA b owns rows [32b, 32b+32); warp w handles rows 32b+w and 32b+16+w.
//    Lane l holds A[row, 32l..32l+31] in regs for both rows (A=0.9I+0.1A_raw).
//    Arrival: red.release.add (32*27=864 cyc serialize).  Detect: thread0
//    ld.cg poll + nanosleep(100) => read pressure ~0.08/cyc < measured 0.14
//    liveness threshold; fence.acq_rel once after detect.
// ---------------------------------------------------------------------------
__global__ __launch_bounds__(RNN_THREADS, 1) void rnn_scan_kernel(
    const float* __restrict__ A_raw,  // (1024, 1024)
    const float* __restrict__ h0,     // (1024,)
    float* __restrict__ out)          // (16384, 1024)
{
    __shared__ int s_abort;
    const int b  = blockIdx.x;
    const int w  = threadIdx.x >> 5;
    const int l  = threadIdx.x & 31;
    const int r0 = b * ROWS_PER_CTA + w;        // rows 0..15 of the CTA block
    const int r1 = r0 + 16;                     // rows 16..31

    if (threadIdx.x == 0) s_abort = 0;

    // Load A rows r0, r1 segments into registers, folding A = 0.9*I + 0.1*A_raw
    float4 a0[8], a1[8];
#pragma unroll
    for (int i = 0; i < 8; i++) {
        int col  = 32 * l + 4 * i;
        float4 v = *(const float4*)&A_raw[(size_t)r0 * HDIM + col];
        v.x *= 0.1f; v.y *= 0.1f; v.z *= 0.1f; v.w *= 0.1f;
        int d = r0 - col;
        if (d == 0) v.x += 0.9f;
        else if (d == 1) v.y += 0.9f;
        else if (d == 2) v.z += 0.9f;
        else if (d == 3) v.w += 0.9f;
        a0[i] = v;

        float4 u = *(const float4*)&A_raw[(size_t)r1 * HDIM + col];
        u.x *= 0.1f; u.y *= 0.1f; u.z *= 0.1f; u.w *= 0.1f;
        int e = r1 - col;
        if (e == 0) u.x += 0.9f;
        else if (e == 1) u.y += 0.9f;
        else if (e == 2) u.z += 0.9f;
        else if (e == 3) u.w += 0.9f;
        a1[i] = u;
    }
    __syncthreads();

    const float* hprev = h0;

    for (int t = 0; t < T_STEPS; t++) {
        // bias prefetch (independent of h -> overlaps wait)
        float bxv = 0.0f;
        if (l == 0)       bxv = g_bx[(size_t)t * HDIM + r0];
        else if (l == 16) bxv = g_bx[(size_t)t * HDIM + r1];

        if (t > 0) {
            if (threadIdx.x == 0) {
                const int* cp = &g_cnt[(size_t)(t - 1) * LINE_INTS];
                int polls = 0;
                for (;;) {
                    if (ldcg_i32(cp) >= NCTA) break;
                    __nanosleep(POLL_SLEEP_NS);     // keep read pressure low
                    if ((++polls & 1023) == 0) {
                        if (ldcg_i32(&g_abort) || polls > WATCHDOG_POLLS) {
                            stg_i32(&g_abort, 1);
                            s_abort = 1;
                            break;
                        }
                    }
                }
                fence_acq();
            }
            __syncthreads();
            if (s_abort) return;   // uniform exit: fallback recomputes
            hprev = out + (size_t)(t - 1) * HDIM;
        }

        // h slice: 32 contiguous elements per lane, shared by both rows
        const float4* h4 = (const float4*)(hprev + 32 * l);
        float p0 = 0.f, p1 = 0.f, q0 = 0.f, q1 = 0.f;
#pragma unroll
        for (int i = 0; i < 8; i++) {
            float4 hv = h4[i];
            p0 = fmaf(a0[i].x, hv.x, p0);
            p1 = fmaf(a0[i].y, hv.y, p1);
            p0 = fmaf(a0[i].z, hv.z, p0);
            p1 = fmaf(a0[i].w, hv.w, p1);
            q0 = fmaf(a1[i].x, hv.x, q0);
            q1 = fmaf(a1[i].y, hv.y, q1);
            q0 = fmaf(a1[i].z, hv.z, q0);
            q1 = fmaf(a1[i].w, hv.w, q1);
        }
        float acc0 = warp_sum(p0 + p1);
        float acc1 = warp_sum(q0 + q1);

        if (l == 0) {
            out[(size_t)t * HDIM + r0] = tanhf(acc0 + bxv);
        } else if (l == 16) {
            out[(size_t)t * HDIM + r1] = tanhf(acc1 + bxv);
        }

        __syncthreads();  // all 32 rows stored before arrival
        if (threadIdx.x == 0) {
            red_release_add(&g_cnt[(size_t)t * LINE_INTS], 1);
        }
    }
}

// ---------------------------------------------------------------------------
// 3) fallback: single-CTA full recompute; runs only if g_abort was set.
// ---------------------------------------------------------------------------
__global__ __launch_bounds__(1024) void fallback_scan_kernel(
    const float* __restrict__ A_raw,
    const float* __restrict__ h0,
    float* __restrict__ out)
{
    if (g_abort == 0) return;

    __shared__ float h[HDIM];
    __shared__ float hn[HDIM];
    const int tid = threadIdx.x;
    const int w   = tid >> 5;
    const int l   = tid & 31;

    h[tid] = h0[tid];
    __syncthreads();

    for (int t = 0; t < T_STEPS; t++) {
        for (int r = w; r < HDIM; r += 32) {
            const float* Ar = A_raw + (size_t)r * HDIM;
            float acc = 0.0f;
#pragma unroll 8
            for (int k = l; k < HDIM; k += 32)
                acc = fmaf(Ar[k], h[k], acc);
#pragma unroll
            for (int s = 16; s > 0; s >>= 1)
                acc += __shfl_xor_sync(0xffffffffu, acc, s);
            if (l == 0) {
                float v = tanhf(0.1f * acc + 0.9f * h[r] +
                                g_bx[(size_t)t * HDIM + r]);
                hn[r] = v;
                out[(size_t)t * HDIM + r] = v;
            }
        }
        __syncthreads();
        h[tid] = hn[tid];
        __syncthreads();
    }
}

// ---------------------------------------------------------------------------
// launch
// ---------------------------------------------------------------------------
extern "C" void kernel_launch(void* const* d_in, const int* in_sizes, int n_in,
                              void* d_out, int out_size) {
    const float* x_seq = (const float*)d_in[0];  // (16384, 256)
    const float* h0    = (const float*)d_in[1];  // (1024,)
    const float* A_raw = (const float*)d_in[2];  // (1024, 1024)
    const float* B     = (const float*)d_in[3];  // (1024, 256)
    const float* c     = (const float*)d_in[4];  // (1024,)
    float* out = (float*)d_out;                  // (16384, 1024)

    init_cnt_kernel<<<64, 1024>>>();
    gemm_bx_kernel<<<dim3(HDIM / 64, T_STEPS / 128), 256>>>(x_seq, B, c);
    rnn_scan_kernel<<<NCTA, RNN_THREADS>>>(A_raw, h0, out);
    fallback_scan_kernel<<<1, 1024>>>(A_raw, h0, out);
}